// round 7
// baseline (speedup 1.0000x reference)
#include <cuda_runtime.h>
#include <math.h>
#include <stdint.h>

// ---------------------------------------------------------------------------
// Round 7: two-kernel split + cp.async double-buffered GEMM pipeline.
//  K1: features -> g_feat tiles [blk][chunk][32k][64m] (coalesced streamer).
//  K2: GEMM1 (async-pipelined chunks, 1 barrier each) -> SiLU -> GEMM2 ->
//      staged epilogue -> sorted segment-sum pool.
// ---------------------------------------------------------------------------

#define MTILE 64
#define NTHREADS 256
#define NCHUNK 10
#define CHUNK_FLOATS 2048          // 32 k-rows x 64 nodes
#define MAXBLK 3200

__device__ float g_feat[(size_t)MAXBLK * NCHUNK * CHUNK_FLOATS];

typedef unsigned long long ull;

__device__ __forceinline__ ull pk2(float x, float y) {
    ull r; asm("mov.b64 %0, {%1, %2};" : "=l"(r) : "f"(x), "f"(y)); return r;
}
__device__ __forceinline__ void upk2(float& x, float& y, ull v) {
    asm("mov.b64 {%0, %1}, %2;" : "=f"(x), "=f"(y) : "l"(v));
}
__device__ __forceinline__ void fma2(ull& d, ull a, ull b) {
    asm("fma.rn.f32x2 %0, %1, %2, %0;" : "+l"(d) : "l"(a), "l"(b));
}
__device__ __forceinline__ void cpa16(uint32_t dst, const void* src) {
    asm volatile("cp.async.cg.shared.global [%0], [%1], 16;" :: "r"(dst), "l"(src));
}

// ============================ kernel 1: features ============================
#define K1_FEAT   0                 // [32][65] = 2080 floats (pitch 65: STS conflict-free)
#define K1_STAGE  2080              // 64*164 = 10496 -> end 12576
#define K1_SMEM_BYTES (12576 * 4)

__global__ void __launch_bounds__(NTHREADS, 4)
feature_kernel(const float* __restrict__ h,
               const float* __restrict__ v,
               const float* __restrict__ t,
               int N)
{
    extern __shared__ float s[];
    float4* stage4 = reinterpret_cast<float4*>(&s[K1_STAGE]);
    const int tid = threadIdx.x;
    const int m0  = blockIdx.x * MTILE;
    const int mlim = (N - m0 < MTILE) ? (N - m0) : MTILE;
    float* outb = &g_feat[(size_t)blockIdx.x * NCHUNK * CHUNK_FLOATS];
    const float4 z4 = make_float4(0.f, 0.f, 0.f, 0.f);

    for (int c = 0; c < NCHUNK; ++c) {
        if (c < 4) {
            // h transpose: channels c*32 .. c*32+31
            const int kc = c * 32;
            for (int i = tid; i < MTILE * 32; i += NTHREADS) {
                int m = i >> 5, k = i & 31;
                float val = (m < mlim) ? h[(size_t)(m0 + m) * 128 + kc + k] : 0.f;
                s[K1_FEAT + k * 65 + m] = val;
            }
        } else if (c < 6) {
            // v norms: channels (c-4)*32 ..
            const int j0 = (c - 4) * 32;
            for (int i = tid; i < MTILE * 24; i += NTHREADS) {
                int nd = i / 24, q = i - nd * 24;
                stage4[nd * 24 + q] = (nd < mlim)
                    ? reinterpret_cast<const float4*>(v)[
                          (size_t)(m0 + nd) * 48 + (j0 >> 2) * 3 + q]
                    : z4;
            }
            __syncthreads();
            for (int i = tid; i < MTILE * 32; i += NTHREADS) {
                int m = i >> 5, k = i & 31;
                const float* sp = &s[K1_STAGE + m * 96 + k * 3];
                s[K1_FEAT + k * 65 + m] =
                    sqrtf(sp[0]*sp[0] + sp[1]*sp[1] + sp[2]*sp[2]);
            }
        } else {
            // t invariants: 16 tensor channels -> 32 feature rows
            const int c0 = (c - 6) * 16;
            for (int i = tid; i < MTILE * 36; i += NTHREADS) {
                int nd = i / 36, q = i - nd * 36;
                stage4[nd * 41 + q] = (nd < mlim)
                    ? reinterpret_cast<const float4*>(t)[
                          (size_t)(m0 + nd) * 144 + (c0 >> 2) * 9 + q]
                    : z4;
            }
            __syncthreads();
            for (int i = tid; i < MTILE * 16; i += NTHREADS) {
                int m = i >> 4, cc = i & 15;
                const float* sp = &s[K1_STAGE + m * 164 + cc * 9];
                float q0 = sp[0], q1 = sp[1], q2 = sp[2];
                float q3 = sp[3], q4 = sp[4], q5 = sp[5];
                float q6 = sp[6], q7 = sp[7], q8 = sp[8];
                float tr = q0 + q4 + q8;
                float fb = sqrtf(q0*q0 + q1*q1 + q2*q2 + q3*q3 + q4*q4 +
                                 q5*q5 + q6*q6 + q7*q7 + q8*q8);
                s[K1_FEAT + (2 * cc)     * 65 + m] = tr;
                s[K1_FEAT + (2 * cc + 1) * 65 + m] = fb;
            }
        }
        __syncthreads();
        // write tile [32][64] coalesced
        for (int i = tid; i < CHUNK_FLOATS; i += NTHREADS) {
            int k = i >> 6, m = i & 63;
            outb[c * CHUNK_FLOATS + i] = s[K1_FEAT + k * 65 + m];
        }
        __syncthreads();
    }
}

// ========================= kernel 2: GEMM + epilogue ========================
// smem float offsets (phases overlaid, separated by barriers)
#define OFF_FA     0            // feat bufs [2][2048] = 4096
#define OFF_W1B    4096         // W1 bufs  [2][5120] = 10240 (end 14336)
#define OFF_HT     0            // hT [160][68] = 10880 (phase 2)
#define OFF_ALPHA  0            // alpha [64][65] = 4160 (phase 3+)
#define OFF_GS     4160         // Gs [64][9] = 576
#define OFF_BATCH  4736         // batch[64] ints
#define OFF_EST    4800         // epilogue t stage 64*164 = 10496 (end 15296)
#define K2_SMEM_FLOATS 15296
#define K2_SMEM_BYTES  (K2_SMEM_FLOATS * 4)

__global__ void __launch_bounds__(NTHREADS, 3)
gemm_pool_kernel(const float* __restrict__ t,
                 const float* __restrict__ frames,
                 const int* __restrict__ batch,
                 const float* __restrict__ W1,
                 const float* __restrict__ b1,
                 const float* __restrict__ W2,
                 const float* __restrict__ b2,
                 float* __restrict__ out,
                 int N, int num_graphs)
{
    extern __shared__ float s[];
    const int tid = threadIdx.x;
    const int m0  = blockIdx.x * MTILE;
    const int mlim = (N - m0 < MTILE) ? (N - m0) : MTILE;
    const uint32_t sbase = (uint32_t)__cvta_generic_to_shared(s);
    const float* featb = &g_feat[(size_t)blockIdx.x * NCHUNK * CHUNK_FLOATS];

    // ---------------- GEMM1: async double-buffered over 10 chunks -----------
    const int tm = (tid & 15) * 4;     // 4 node-rows
    const int tn = (tid >> 4) * 10;    // 10 hidden cols (5 packed pairs)

    ull accp[4][5];
#pragma unroll
    for (int i = 0; i < 4; ++i)
#pragma unroll
        for (int j = 0; j < 5; ++j) accp[i][j] = 0ULL;

#define ISSUE_CHUNK(c)                                                        \
    do {                                                                      \
        const int _b = (c) & 1;                                               \
        const float* fsrc = featb + (c) * CHUNK_FLOATS;                       \
        uint32_t fdst = sbase + (OFF_FA + _b * 2048) * 4;                     \
        for (int i = tid; i < 512; i += NTHREADS)                             \
            cpa16(fdst + i * 16, fsrc + i * 4);                               \
        const float* wsrc = W1 + (size_t)(c) * 5120;                          \
        uint32_t wdst = sbase + (OFF_W1B + _b * 5120) * 4;                    \
        for (int i = tid; i < 1280; i += NTHREADS)                            \
            cpa16(wdst + i * 16, wsrc + i * 4);                               \
        asm volatile("cp.async.commit_group;");                               \
    } while (0)

    ISSUE_CHUNK(0);
    for (int c = 0; c < NCHUNK; ++c) {
        asm volatile("cp.async.wait_group 0;");
        __syncthreads();                       // chunk c visible; FMA(c-1) done
        if (c + 1 < NCHUNK) ISSUE_CHUNK(c + 1);

        const float* fb = &s[OFF_FA  + (c & 1) * 2048];
        const float* wb = &s[OFF_W1B + (c & 1) * 5120];
#pragma unroll 4
        for (int k = 0; k < 32; ++k) {
            const float4 a4 = *reinterpret_cast<const float4*>(&fb[k * 64 + tm]);
            ull avd[4];
            avd[0] = pk2(a4.x, a4.x);
            avd[1] = pk2(a4.y, a4.y);
            avd[2] = pk2(a4.z, a4.z);
            avd[3] = pk2(a4.w, a4.w);
            const ull* bp = reinterpret_cast<const ull*>(&wb[k * 160 + tn]);
            ull bv2[5];
#pragma unroll
            for (int j = 0; j < 5; ++j) bv2[j] = bp[j];
#pragma unroll
            for (int i = 0; i < 4; ++i)
#pragma unroll
                for (int j = 0; j < 5; ++j)
                    fma2(accp[i][j], avd[i], bv2[j]);
        }
    }
    __syncthreads();   // buffers dead; hT overlays

    // ---------------- bias + SiLU -> hT [160][68] ---------------------------
#pragma unroll
    for (int j2 = 0; j2 < 5; ++j2) {
        const float b_lo = b1[tn + 2 * j2];
        const float b_hi = b1[tn + 2 * j2 + 1];
#pragma unroll
        for (int i = 0; i < 4; ++i) {
            float lo, hi;
            upk2(lo, hi, accp[i][j2]);
            float x0 = lo + b_lo, x1 = hi + b_hi;
            s[OFF_HT + (tn + 2 * j2)     * 68 + tm + i] = x0 / (1.0f + __expf(-x0));
            s[OFF_HT + (tn + 2 * j2 + 1) * 68 + tm + i] = x1 / (1.0f + __expf(-x1));
        }
    }
    __syncthreads();

    // ---------------- GEMM2: [64,160] @ [160,64] ----------------------------
    const int tn2 = (tid >> 4) * 4;
    ull acc2p[4][2];
#pragma unroll
    for (int i = 0; i < 4; ++i) { acc2p[i][0] = 0ULL; acc2p[i][1] = 0ULL; }

#pragma unroll 4
    for (int k = 0; k < 160; ++k) {
        const float4 a4 = *reinterpret_cast<const float4*>(&s[OFF_HT + k * 68 + tm]);
        const ulonglong2 b2v = *reinterpret_cast<const ulonglong2*>(
            &W2[(size_t)k * 64 + tn2]);
        ull avd[4];
        avd[0] = pk2(a4.x, a4.x);
        avd[1] = pk2(a4.y, a4.y);
        avd[2] = pk2(a4.z, a4.z);
        avd[3] = pk2(a4.w, a4.w);
#pragma unroll
        for (int i = 0; i < 4; ++i) {
            fma2(acc2p[i][0], avd[i], b2v.x);
            fma2(acc2p[i][1], avd[i], b2v.y);
        }
    }
    __syncthreads();   // hT dead; alpha overlays

    // alphas + batch -> smem
    {
        const float b_0 = b2[tn2 + 0], b_1 = b2[tn2 + 1];
        const float b_2 = b2[tn2 + 2], b_3 = b2[tn2 + 3];
#pragma unroll
        for (int i = 0; i < 4; ++i) {
            float a0, a1, a2, a3;
            upk2(a0, a1, acc2p[i][0]);
            upk2(a2, a3, acc2p[i][1]);
            float* ap = &s[OFF_ALPHA + (tm + i) * 65 + tn2];
            ap[0] = a0 + b_0;
            ap[1] = a1 + b_1;
            ap[2] = a2 + b_2;
            ap[3] = a3 + b_3;
        }
    }
    if (tid < MTILE)
        reinterpret_cast<int*>(s)[OFF_BATCH + tid] =
            (tid < mlim) ? batch[m0 + tid] : -1;
    __syncthreads();

    // ---------------- epilogue: staged gated sum over 4 t-chunks ------------
    float4* stage4 = reinterpret_cast<float4*>(&s[OFF_EST]);
    const int node = tid >> 2;
    const int jj   = tid & 3;
    float g[9];
#pragma unroll
    for (int k = 0; k < 9; ++k) g[k] = 0.0f;

    const float4 z4 = make_float4(0.f, 0.f, 0.f, 0.f);
    for (int chunk = 0; chunk < 4; ++chunk) {
        for (int i = tid; i < MTILE * 36; i += NTHREADS) {
            int nd = i / 36, q = i - nd * 36;
            stage4[nd * 41 + q] = (nd < mlim)
                ? reinterpret_cast<const float4*>(t)[
                      (size_t)(m0 + nd) * 144 + chunk * 36 + q]
                : z4;
        }
        __syncthreads();
        if (node < mlim) {
            const float* ap = &s[OFF_ALPHA + node * 65 + chunk * 16];
#pragma unroll
            for (int cc = 0; cc < 4; ++cc) {
                const int ch = jj + 4 * cc;
                const float al = ap[ch];
                const float* f = &s[OFF_EST + node * 164 + ch * 9];
#pragma unroll
                for (int k = 0; k < 9; ++k)
                    g[k] = fmaf(al, f[k], g[k]);
            }
        }
        __syncthreads();
    }

#pragma unroll
    for (int k = 0; k < 9; ++k) {
        g[k] += __shfl_xor_sync(0xFFFFFFFFu, g[k], 1);
        g[k] += __shfl_xor_sync(0xFFFFFFFFu, g[k], 2);
    }

    if (jj == 0) {
        float G[9];
        if (node < mlim) {
            float S[9];
#pragma unroll
            for (int a = 0; a < 3; ++a)
#pragma unroll
                for (int b = 0; b < 3; ++b)
                    S[a * 3 + b] = 0.5f * (g[a * 3 + b] + g[b * 3 + a]);
            const float* rp = frames + (size_t)(m0 + node) * 9;
            float R[9];
#pragma unroll
            for (int k = 0; k < 9; ++k) R[k] = rp[k];
            float P[9];
#pragma unroll
            for (int a = 0; a < 3; ++a)
#pragma unroll
                for (int c = 0; c < 3; ++c)
                    P[a * 3 + c] = R[a * 3 + 0] * S[0 * 3 + c]
                                 + R[a * 3 + 1] * S[1 * 3 + c]
                                 + R[a * 3 + 2] * S[2 * 3 + c];
#pragma unroll
            for (int a = 0; a < 3; ++a)
#pragma unroll
                for (int d = 0; d < 3; ++d)
                    G[a * 3 + d] = P[a * 3 + 0] * R[d * 3 + 0]
                                 + P[a * 3 + 1] * R[d * 3 + 1]
                                 + P[a * 3 + 2] * R[d * 3 + 2];
        } else {
#pragma unroll
            for (int k = 0; k < 9; ++k) G[k] = 0.0f;
        }
#pragma unroll
        for (int k = 0; k < 9; ++k) s[OFF_GS + node * 9 + k] = G[k];
    }
    __syncthreads();

    // ---------------- sorted-run segment sum --------------------------------
    if (tid < 9) {
        const int* bs = reinterpret_cast<const int*>(s) + OFF_BATCH;
        int cur = bs[0];
        float run = 0.0f;
        for (int n = 0; n < mlim; ++n) {
            int b = bs[n];
            if (b != cur) {
                if ((unsigned)cur < (unsigned)num_graphs)
                    atomicAdd(&out[(size_t)cur * 9 + tid], run);
                run = 0.0f;
                cur = b;
            }
            run += s[OFF_GS + n * 9 + tid];
        }
        if ((unsigned)cur < (unsigned)num_graphs)
            atomicAdd(&out[(size_t)cur * 9 + tid], run);
    }
}

// ================================ launcher ==================================
extern "C" void kernel_launch(void* const* d_in, const int* in_sizes, int n_in,
                              void* d_out, int out_size)
{
    const float* h      = (const float*)d_in[0];
    const float* v      = (const float*)d_in[1];
    const float* t      = (const float*)d_in[2];
    const float* frames = (const float*)d_in[3];
    const int*   batch  = (const int*)d_in[4];
    const float* W1     = (const float*)d_in[5];
    const float* b1     = (const float*)d_in[6];
    const float* W2     = (const float*)d_in[7];
    const float* b2     = (const float*)d_in[8];
    float* out = (float*)d_out;

    const int N = in_sizes[0] / 128;
    const int num_graphs = out_size / 9;
    const int grid = (N + MTILE - 1) / MTILE;

    cudaMemsetAsync(d_out, 0, (size_t)out_size * sizeof(float));

    cudaFuncSetAttribute(feature_kernel,
                         cudaFuncAttributeMaxDynamicSharedMemorySize, K1_SMEM_BYTES);
    cudaFuncSetAttribute(gemm_pool_kernel,
                         cudaFuncAttributeMaxDynamicSharedMemorySize, K2_SMEM_BYTES);

    feature_kernel<<<grid, NTHREADS, K1_SMEM_BYTES>>>(h, v, t, N);
    gemm_pool_kernel<<<grid, NTHREADS, K2_SMEM_BYTES>>>(
        t, frames, batch, W1, b1, W2, b2, out, N, num_graphs);
}